// round 13
// baseline (speedup 1.0000x reference)
#include <cuda_runtime.h>
#include <math.h>

#define N_TOK 2000
#define C_DIM 256
#define C3    768
#define H_NUM 8
#define ROWS  8
#define NCTA  250
#define TPB   512
#define KT_LD 2048   // padded j-stride of transposed operands

// ---------------- scratch (static device globals; no allocation) ----------------
static __device__ float g_yc [N_TOK * C3];        // qkv_cls [2000,768]
static __device__ float g_yr [N_TOK * C3];        // qkv_reg
static __device__ float g_qnc[N_TOK * C_DIM];     // normalized q_cls, row-major
static __device__ float g_qnr[N_TOK * C_DIM];
static __device__ float g_vn [N_TOK * C_DIM];     // normalized v_cls, row-major
static __device__ float g_ktc[C_DIM * KT_LD];     // normalized k_cls, TRANSPOSED [chan][j]
static __device__ float g_ktr[C_DIM * KT_LD];     // normalized k_reg, transposed
static __device__ float g_vnt[C_DIM * KT_LD];     // normalized v_cls, transposed

__device__ __forceinline__ float warpSum(float v) {
    #pragma unroll
    for (int o = 16; o; o >>= 1) v += __shfl_xor_sync(0xffffffffu, v, o);
    return v;
}

// ---------------- packed fp32x2 helpers (Blackwell FFMA2, PTX-only) ----------------
__device__ __forceinline__ unsigned long long fma2(unsigned long long a,
                                                   unsigned long long b,
                                                   unsigned long long c) {
    unsigned long long d;
    asm("fma.rn.f32x2 %0, %1, %2, %3;" : "=l"(d) : "l"(a), "l"(b), "l"(c));
    return d;
}
__device__ __forceinline__ unsigned long long pack2(float lo, float hi) {
    unsigned long long d;
    asm("mov.b64 %0, {%1, %2};" : "=l"(d) : "f"(lo), "f"(hi));
    return d;
}
__device__ __forceinline__ float2 unpack2(unsigned long long v) {
    float2 r;
    asm("mov.b64 {%0, %1}, %2;" : "=f"(r.x), "=f"(r.y) : "l"(v));
    return r;
}

// ---------------- GEMM NN:  C[M,N] = A[M,K] * B[K,N] ----------------
__global__ void sgemm_nn(const float* __restrict__ A, const float* __restrict__ B,
                         float* __restrict__ C, int M, int Nn, int K,
                         int lda, int ldb, int ldc) {
    __shared__ float As[64][33];
    __shared__ float Bs[32][65];
    int tid = threadIdx.x;
    int tx = tid & 15, ty = tid >> 4;
    int m0 = blockIdx.y * 64, n0 = blockIdx.x * 64;
    float acc[4][4] = {};
    for (int k0 = 0; k0 < K; k0 += 32) {
        #pragma unroll
        for (int p = 0; p < 8; ++p) {
            int idx = tid + p * 256;
            int r = idx >> 5, k = idx & 31;
            As[r][k] = (m0 + r < M) ? A[(size_t)(m0 + r) * lda + k0 + k] : 0.f;
            int kk = idx >> 6, nn = idx & 63;
            if (kk < 32)
                Bs[kk][nn] = (n0 + nn < Nn) ? B[(size_t)(k0 + kk) * ldb + n0 + nn] : 0.f;
        }
        __syncthreads();
        #pragma unroll
        for (int k = 0; k < 32; ++k) {
            float ra[4], rb[4];
            #pragma unroll
            for (int x = 0; x < 4; ++x) { ra[x] = As[ty * 4 + x][k]; rb[x] = Bs[k][tx * 4 + x]; }
            #pragma unroll
            for (int mi = 0; mi < 4; ++mi)
                #pragma unroll
                for (int ni = 0; ni < 4; ++ni) acc[mi][ni] += ra[mi] * rb[ni];
        }
        __syncthreads();
    }
    #pragma unroll
    for (int mi = 0; mi < 4; ++mi) {
        int gm = m0 + ty * 4 + mi;
        if (gm >= M) continue;
        #pragma unroll
        for (int ni = 0; ni < 4; ++ni) {
            int gn = n0 + tx * 4 + ni;
            if (gn < Nn) C[(size_t)gm * ldc + gn] = acc[mi][ni];
        }
    }
}

// ---------------- per-head L2 normalize + transposes + x_ori ----------------
__device__ __forceinline__ float normed_val(const float* __restrict__ src, int base, int t) {
    float v = src[base + t];
    float ss = warpSum(v * v);          // warp == one 32-dim head segment
    return v / (sqrtf(ss) + 1e-8f);
}
__global__ void normalize_kernel(const float* __restrict__ yc, const float* __restrict__ yr,
                                 float* __restrict__ out) {
    int n = blockIdx.x;
    int t = threadIdx.x;                // 256 threads, 8 warps == 8 heads
    int b = n * C3;
    float qc = normed_val(yc, b + 0,   t);  g_qnc[n * C_DIM + t] = qc;
    float kc = normed_val(yc, b + 256, t);  g_ktc[t * KT_LD + n] = kc;
    float vv = normed_val(yc, b + 512, t);  g_vn[n * C_DIM + t] = vv;
                                            g_vnt[t * KT_LD + n] = vv;
    float qr = normed_val(yr, b + 0,   t);  g_qnr[n * C_DIM + t] = qr;
    float kr = normed_val(yr, b + 256, t);  g_ktr[t * KT_LD + n] = kr;
    out[(size_t)n * 512 + 256 + t] = yc[b + 512 + t];   // x_ori half of x_out
}

// ================= mega-fused attention kernel (f32x2 + SW pipeline) =================
// smem float layout:
//   [0     .. 16000) expc  (8 rows x 2000)   -> becomes combined masked p in phase B
//   [16000 .. 32000) expr
//   [32000 .. 48000) simb  (8 rows x 2000)
//   [48000 .. 49024) qsd   (phase A: 2 br x 8 rows x 32 ch, DUPLICATED float2)
//   [48000 .. 52096) scrvd (phase C: 8 vn rows x 256 ch, DUPLICATED float2) — overlaps qsd
//   [52096 .. 56192) pav   (AV partials: 16 warps x 8r x 32d)
//   [56192 .. 56224) misc: [0..7] cls inv, [8..15] reg inv, [16..23] s2 inv, [24..31] tot inv
#define SMEM_FLOATS 56224

__global__ __launch_bounds__(TPB, 1) void fused_attn(float* __restrict__ out,
                                                     float* __restrict__ out_sim) {
    extern __shared__ float sm[];
    float* expc = sm;
    float* expr = sm + 16000;
    float* simb = sm + 32000;
    unsigned long long* qsd   = (unsigned long long*)(sm + 48000);
    unsigned long long* scrvd = (unsigned long long*)(sm + 48000);
    float* pav  = sm + 52096;
    float* misc = sm + 56192;

    const int tid  = threadIdx.x;
    const int lane = tid & 31;
    const int wrp  = tid >> 5;
    const int i0   = blockIdx.x * ROWS;

    // phase A map: branch x 256 j-threads (4 j each, 2 passes)
    const int bA = tid >> 8;            // 0=cls, 1=reg (warp-uniform)
    const int jt = tid & 255;
    const float* ktA = bA ? g_ktr : g_ktc;
    float* ebA = bA ? expr : expc;
    const int boff = bA * 256;

    // zero sim accumulator
    for (int k = tid; k < ROWS * N_TOK; k += TPB) simb[k] = 0.f;

    for (int h = 0; h < H_NUM; ++h) {
        // ======== phase A: scores -> exp -> row sums (k streamed from L2, FFMA2, pipelined) ========
        if (tid < 16) misc[tid] = 0.f;
        {   // load q tiles duplicated: 512 entries = 2 branches x 8 rows x 32 ch
            int b2 = tid >> 8, r = (tid >> 5) & 7, kk = tid & 31;
            const float* qsrc = b2 ? g_qnr : g_qnc;
            float q = qsrc[(i0 + r) * C_DIM + h * 32 + kk];
            qsd[tid] = pack2(q, q);
        }
        __syncthreads();

        float psum[ROWS];
        #pragma unroll
        for (int r = 0; r < ROWS; ++r) psum[r] = 0.f;

        #pragma unroll
        for (int pass = 0; pass < 2; ++pass) {
            int j = pass * 1024 + jt * 4;
            if (j < N_TOK) {
                unsigned long long c2[ROWS][2];
                #pragma unroll
                for (int r = 0; r < ROWS; ++r) { c2[r][0] = 0ULL; c2[r][1] = 0ULL; }
                const float* ktb = ktA + (size_t)(h * 32) * KT_LD + j;
                ulonglong2 kvc[4], kvn[4];
                #pragma unroll
                for (int u = 0; u < 4; ++u)
                    kvc[u] = *(const ulonglong2*)&ktb[(size_t)u * KT_LD];
                #pragma unroll
                for (int cg = 0; cg < 8; ++cg) {
                    if (cg < 7) {   // prefetch next channel group
                        #pragma unroll
                        for (int u = 0; u < 4; ++u)
                            kvn[u] = *(const ulonglong2*)&ktb[(size_t)((cg + 1) * 4 + u) * KT_LD];
                    }
                    #pragma unroll
                    for (int u = 0; u < 4; ++u) {
                        #pragma unroll
                        for (int r = 0; r < ROWS; ++r) {
                            unsigned long long qd = qsd[boff + r * 32 + cg * 4 + u];
                            c2[r][0] = fma2(qd, kvc[u].x, c2[r][0]);
                            c2[r][1] = fma2(qd, kvc[u].y, c2[r][1]);
                        }
                    }
                    #pragma unroll
                    for (int u = 0; u < 4; ++u) kvc[u] = kvn[u];
                }
                #pragma unroll
                for (int r = 0; r < ROWS; ++r) {
                    float2 lo = unpack2(c2[r][0]);
                    float2 hi = unpack2(c2[r][1]);
                    float4 e;
                    e.x = __expf(fmaf(lo.x, 25.f, -25.f));
                    e.y = __expf(fmaf(lo.y, 25.f, -25.f));
                    e.z = __expf(fmaf(hi.x, 25.f, -25.f));
                    e.w = __expf(fmaf(hi.y, 25.f, -25.f));
                    *(float4*)&ebA[r * 2000 + j] = e;
                    psum[r] += (e.x + e.y) + (e.z + e.w);
                }
            }
        }
        #pragma unroll
        for (int r = 0; r < ROWS; ++r) {
            float s = warpSum(psum[r]);
            if (lane == 0) atomicAdd(&misc[bA * 8 + r], s);
        }
        __syncthreads();
        if (tid < 16) misc[tid] = 1.0f / misc[tid];
        __syncthreads();

        // ======== phase B1: combine + mask (p overwrites expc) + sim accumulate ========
        for (int idx = tid; idx < 4000; idx += TPB) {   // 4000 float4 groups
            int r = idx / 500;
            int j = (idx - r * 500) * 4;
            float4 ec = *(const float4*)&expc[r * 2000 + j];
            float4 er = *(const float4*)&expr[r * 2000 + j];
            float ic = misc[r], ir = misc[8 + r];
            float4 p;
            p.x = 0.5f * fmaf(ec.x, ic, er.x * ir);
            p.y = 0.5f * fmaf(ec.y, ic, er.y * ir);
            p.z = 0.5f * fmaf(ec.z, ic, er.z * ir);
            p.w = 0.5f * fmaf(ec.w, ic, er.w * ir);
            int i = i0 + r, bs = (i / 10) * 10;
            if (!((j + 0 == i) || (j + 0 < bs) || (j + 0 >= bs + 9))) p.x = 0.f;
            if (!((j + 1 == i) || (j + 1 < bs) || (j + 1 >= bs + 9))) p.y = 0.f;
            if (!((j + 2 == i) || (j + 2 < bs) || (j + 2 >= bs + 9))) p.z = 0.f;
            if (!((j + 3 == i) || (j + 3 < bs) || (j + 3 >= bs + 9))) p.w = 0.f;
            float4 sb = *(const float4*)&simb[r * 2000 + j];
            sb.x += p.x; sb.y += p.y; sb.z += p.z; sb.w += p.w;
            *(float4*)&simb[r * 2000 + j] = sb;
            *(float4*)&expc[r * 2000 + j] = p;
        }
        __syncthreads();

        // ======== phase B2: AV (x = p @ v), 16 warps x 128-j slices, FFMA2, pipelined ========
        {
            int jbase = wrp * 128;
            int cnt = N_TOK - jbase; if (cnt > 128) cnt = 128;
            unsigned long long acc2[ROWS];
            #pragma unroll
            for (int r = 0; r < ROWS; ++r) acc2[r] = 0ULL;
            const float* vp = g_yc + 512 + h * 32 + lane;
            float v0 = vp[(size_t)(jbase + 0) * C3];
            float v1 = vp[(size_t)(jbase + 1) * C3];
            float v2 = vp[(size_t)(jbase + 2) * C3];
            float v3 = vp[(size_t)(jbase + 3) * C3];
            for (int jj = 0; jj < cnt; jj += 4) {
                int j = jbase + jj;
                float n0, n1, n2, n3;
                if (jj + 4 < cnt) {   // prefetch next 4 v
                    n0 = vp[(size_t)(j + 4) * C3];
                    n1 = vp[(size_t)(j + 5) * C3];
                    n2 = vp[(size_t)(j + 6) * C3];
                    n3 = vp[(size_t)(j + 7) * C3];
                }
                unsigned long long vA = pack2(v0, v1);
                unsigned long long vB = pack2(v2, v3);
                #pragma unroll
                for (int r = 0; r < ROWS; ++r) {
                    ulonglong2 p2 = *(const ulonglong2*)&expc[r * 2000 + j];  // broadcast
                    acc2[r] = fma2(p2.x, vA, acc2[r]);
                    acc2[r] = fma2(p2.y, vB, acc2[r]);
                }
                v0 = n0; v1 = n1; v2 = n2; v3 = n3;
            }
            #pragma unroll
            for (int r = 0; r < ROWS; ++r) {
                float2 t = unpack2(acc2[r]);
                pav[wrp * 256 + r * 32 + lane] = t.x + t.y;
            }
        }
        __syncthreads();
        if (tid < 256) {
            int r = tid >> 5, d = tid & 31;
            float s = 0.f;
            #pragma unroll
            for (int w2 = 0; w2 < 16; ++w2) s += pav[w2 * 256 + tid];
            out[(size_t)(i0 + r) * 512 + h * 32 + d] = s;
        }
        __syncthreads();
    }

    // ======== phase C: raw = vn.vn^T mask + sim_round2 (FFMA2, pipelined) ========
    {   // vn rows of this block -> scrvd duplicated (8 x 256 float2)
        int r = tid >> 6, cc = (tid & 63) * 4;
        float4 v = *(const float4*)&g_vn[(i0 + r) * C_DIM + cc];
        scrvd[r * 256 + cc + 0] = pack2(v.x, v.x);
        scrvd[r * 256 + cc + 1] = pack2(v.y, v.y);
        scrvd[r * 256 + cc + 2] = pack2(v.z, v.z);
        scrvd[r * 256 + cc + 3] = pack2(v.w, v.w);
    }
    if (tid >= 16 && tid < 32) misc[tid] = 0.f;   // clear [16..31]
    __syncthreads();
    {   // denominators: sum_j exp(sim[r][j])
        int r = wrp & 7, half = wrp >> 3;
        float s = 0.f;
        for (int j = half * 1000 + lane * 4; j < half * 1000 + 1000; j += 128) {
            float4 sb = *(const float4*)&simb[r * 2000 + j];
            s += __expf(sb.x) + __expf(sb.y) + __expf(sb.z) + __expf(sb.w);
        }
        s = warpSum(s);
        if (lane == 0) atomicAdd(&misc[16 + r], s);
    }
    __syncthreads();
    if (tid < 8) misc[16 + tid] = 1.0f / misc[16 + tid];
    __syncthreads();
    {   // stream vnt from L2: raw rows, then mask + exp + renorm prep
        int j = tid * 4;
        float tot[ROWS];
        #pragma unroll
        for (int r = 0; r < ROWS; ++r) tot[r] = 0.f;
        if (j < N_TOK) {
            unsigned long long c2[ROWS][2];
            #pragma unroll
            for (int r = 0; r < ROWS; ++r) { c2[r][0] = 0ULL; c2[r][1] = 0ULL; }
            const float* vt = g_vnt + j;
            ulonglong2 kvc[4], kvn[4];
            #pragma unroll
            for (int u = 0; u < 4; ++u)
                kvc[u] = *(const ulonglong2*)&vt[(size_t)u * KT_LD];
            for (int cg = 0; cg < 64; ++cg) {
                if (cg < 63) {   // prefetch next channel group
                    #pragma unroll
                    for (int u = 0; u < 4; ++u)
                        kvn[u] = *(const ulonglong2*)&vt[(size_t)((cg + 1) * 4 + u) * KT_LD];
                }
                #pragma unroll
                for (int u = 0; u < 4; ++u) {
                    #pragma unroll
                    for (int r = 0; r < ROWS; ++r) {
                        unsigned long long qd = scrvd[r * 256 + cg * 4 + u];
                        c2[r][0] = fma2(qd, kvc[u].x, c2[r][0]);
                        c2[r][1] = fma2(qd, kvc[u].y, c2[r][1]);
                    }
                }
                #pragma unroll
                for (int u = 0; u < 4; ++u) kvc[u] = kvn[u];
            }
            #pragma unroll
            for (int r = 0; r < ROWS; ++r) {
                float2 lo = unpack2(c2[r][0]);
                float2 hi = unpack2(c2[r][1]);
                float4 sb = *(const float4*)&simb[r * 2000 + j];
                float inv = misc[16 + r];
                // raw_mean > 0.75  <=>  raw (sum over 8 heads) > 6.0
                float t0 = (lo.x > 6.0f) ? __expf(sb.x) * inv : 0.f;
                float t1 = (lo.y > 6.0f) ? __expf(sb.y) * inv : 0.f;
                float t2 = (hi.x > 6.0f) ? __expf(sb.z) * inv : 0.f;
                float t3 = (hi.y > 6.0f) ? __expf(sb.w) * inv : 0.f;
                sb.x = t0; sb.y = t1; sb.z = t2; sb.w = t3;
                *(float4*)&simb[r * 2000 + j] = sb;
                tot[r] += (t0 + t1) + (t2 + t3);
            }
        }
        #pragma unroll
        for (int r = 0; r < ROWS; ++r) {
            float s = warpSum(tot[r]);
            if (lane == 0) atomicAdd(&misc[24 + r], s);
        }
    }
    __syncthreads();
    if (tid < 8) misc[24 + tid] = 1.0f / (misc[24 + tid] + 1e-8f);
    __syncthreads();
    {   // final store
        int r = wrp & 7, half = wrp >> 3;
        float inv = misc[24 + r];
        for (int j = half * 1000 + lane * 4; j < half * 1000 + 1000; j += 128) {
            float4 sb = *(const float4*)&simb[r * 2000 + j];
            sb.x *= inv; sb.y *= inv; sb.z *= inv; sb.w *= inv;
            *(float4*)&out_sim[(size_t)(i0 + r) * 2000 + j] = sb;
        }
    }
}

// ---------------- launch ----------------
extern "C" void kernel_launch(void* const* d_in, const int* in_sizes, int n_in,
                              void* d_out, int out_size) {
    const float* x_cls = (const float*)d_in[0];
    const float* x_reg = (const float*)d_in[1];
    const float* Wc    = (const float*)d_in[2];
    const float* Wr    = (const float*)d_in[3];
    float* out     = (float*)d_out;
    float* out_sim = out + (size_t)N_TOK * 512;

    float *yc, *yr;
    cudaGetSymbolAddress((void**)&yc, g_yc);
    cudaGetSymbolAddress((void**)&yr, g_yr);

    cudaFuncSetAttribute(fused_attn, cudaFuncAttributeMaxDynamicSharedMemorySize,
                         SMEM_FLOATS * 4);

    // 1) QKV projections
    sgemm_nn<<<dim3(12, 32), 256>>>(x_cls, Wc, yc, N_TOK, C3, C_DIM, C_DIM, C3, C3);
    sgemm_nn<<<dim3(12, 32), 256>>>(x_reg, Wr, yr, N_TOK, C3, C_DIM, C_DIM, C3, C3);

    // 2) per-head L2 normalize + transposes (+ x_ori half of out)
    normalize_kernel<<<N_TOK, 256>>>(yc, yr, out);

    // 3) fully fused attention: scores -> softmax -> mask -> sim -> AV -> raw -> sim_round2
    fused_attn<<<NCTA, TPB, SMEM_FLOATS * 4>>>(out, out_sim);
}

// round 14
// speedup vs baseline: 1.0715x; 1.0715x over previous
#include <cuda_runtime.h>
#include <math.h>

#define N_TOK 2000
#define C_DIM 256
#define C3    768
#define H_NUM 8
#define ROWS  4
#define NCTA  500
#define TPB   256
#define KT_LD 2048   // padded j-stride of transposed operands

// ---------------- scratch (static device globals; no allocation) ----------------
static __device__ float g_yc [N_TOK * C3];        // qkv_cls [2000,768]
static __device__ float g_yr [N_TOK * C3];        // qkv_reg
static __device__ float g_qnc[N_TOK * C_DIM];     // normalized q_cls, row-major
static __device__ float g_qnr[N_TOK * C_DIM];
static __device__ float g_vn [N_TOK * C_DIM];     // normalized v_cls, row-major
static __device__ float g_ktc[C_DIM * KT_LD];     // normalized k_cls, TRANSPOSED [chan][j]
static __device__ float g_ktr[C_DIM * KT_LD];     // normalized k_reg, transposed
static __device__ float g_vnt[C_DIM * KT_LD];     // normalized v_cls, transposed

__device__ __forceinline__ float warpSum(float v) {
    #pragma unroll
    for (int o = 16; o; o >>= 1) v += __shfl_xor_sync(0xffffffffu, v, o);
    return v;
}

// ---------------- packed fp32x2 helpers (Blackwell FFMA2, PTX-only) ----------------
__device__ __forceinline__ unsigned long long fma2(unsigned long long a,
                                                   unsigned long long b,
                                                   unsigned long long c) {
    unsigned long long d;
    asm("fma.rn.f32x2 %0, %1, %2, %3;" : "=l"(d) : "l"(a), "l"(b), "l"(c));
    return d;
}
__device__ __forceinline__ unsigned long long pack2(float lo, float hi) {
    unsigned long long d;
    asm("mov.b64 %0, {%1, %2};" : "=l"(d) : "f"(lo), "f"(hi));
    return d;
}
__device__ __forceinline__ float2 unpack2(unsigned long long v) {
    float2 r;
    asm("mov.b64 {%0, %1}, %2;" : "=f"(r.x), "=f"(r.y) : "l"(v));
    return r;
}

// ---------------- GEMM NN:  C[M,N] = A[M,K] * B[K,N] ----------------
__global__ void sgemm_nn(const float* __restrict__ A, const float* __restrict__ B,
                         float* __restrict__ C, int M, int Nn, int K,
                         int lda, int ldb, int ldc) {
    __shared__ float As[64][33];
    __shared__ float Bs[32][65];
    int tid = threadIdx.x;
    int tx = tid & 15, ty = tid >> 4;
    int m0 = blockIdx.y * 64, n0 = blockIdx.x * 64;
    float acc[4][4] = {};
    for (int k0 = 0; k0 < K; k0 += 32) {
        #pragma unroll
        for (int p = 0; p < 8; ++p) {
            int idx = tid + p * 256;
            int r = idx >> 5, k = idx & 31;
            As[r][k] = (m0 + r < M) ? A[(size_t)(m0 + r) * lda + k0 + k] : 0.f;
            int kk = idx >> 6, nn = idx & 63;
            if (kk < 32)
                Bs[kk][nn] = (n0 + nn < Nn) ? B[(size_t)(k0 + kk) * ldb + n0 + nn] : 0.f;
        }
        __syncthreads();
        #pragma unroll
        for (int k = 0; k < 32; ++k) {
            float ra[4], rb[4];
            #pragma unroll
            for (int x = 0; x < 4; ++x) { ra[x] = As[ty * 4 + x][k]; rb[x] = Bs[k][tx * 4 + x]; }
            #pragma unroll
            for (int mi = 0; mi < 4; ++mi)
                #pragma unroll
                for (int ni = 0; ni < 4; ++ni) acc[mi][ni] += ra[mi] * rb[ni];
        }
        __syncthreads();
    }
    #pragma unroll
    for (int mi = 0; mi < 4; ++mi) {
        int gm = m0 + ty * 4 + mi;
        if (gm >= M) continue;
        #pragma unroll
        for (int ni = 0; ni < 4; ++ni) {
            int gn = n0 + tx * 4 + ni;
            if (gn < Nn) C[(size_t)gm * ldc + gn] = acc[mi][ni];
        }
    }
}

// ---------------- per-head L2 normalize + transposes + x_ori ----------------
__device__ __forceinline__ float normed_val(const float* __restrict__ src, int base, int t) {
    float v = src[base + t];
    float ss = warpSum(v * v);          // warp == one 32-dim head segment
    return v / (sqrtf(ss) + 1e-8f);
}
__global__ void normalize_kernel(const float* __restrict__ yc, const float* __restrict__ yr,
                                 float* __restrict__ out) {
    int n = blockIdx.x;
    int t = threadIdx.x;                // 256 threads, 8 warps == 8 heads
    int b = n * C3;
    float qc = normed_val(yc, b + 0,   t);  g_qnc[n * C_DIM + t] = qc;
    float kc = normed_val(yc, b + 256, t);  g_ktc[t * KT_LD + n] = kc;
    float vv = normed_val(yc, b + 512, t);  g_vn[n * C_DIM + t] = vv;
                                            g_vnt[t * KT_LD + n] = vv;
    float qr = normed_val(yr, b + 0,   t);  g_qnr[n * C_DIM + t] = qr;
    float kr = normed_val(yr, b + 256, t);  g_ktr[t * KT_LD + n] = kr;
    out[(size_t)n * 512 + 256 + t] = yc[b + 512 + t];   // x_ori half of x_out
}

// ================= mega-fused attention kernel (ROWS=4, occ>=2, sim in regs) =================
// smem float layout (70.6 KB -> 2+ CTAs/SM):
//   [0     .. 8000 ) expc  (4 rows x 2000)  -> becomes combined masked p in phase B
//   [8000  .. 16000) expr
//   [16000 .. 16512) qsd   (heads: 2 br x 4 rows x 32 ch, DUPLICATED float2; 256 ull)
//   [16512 .. 17536) pav   (heads: AV partials 8 warps x 4r x 32d)
//   [16000 .. 18048) scrvd (phase C: 4 vn rows x 256 ch dup; 1024 ull) — overlaps qsd+pav
//   [18048 .. 18080) misc: [0..3] cls inv, [8..11] reg inv, [16..19] s2 inv, [24..27] tot inv
#define SMEM_FLOATS 18080

__global__ __launch_bounds__(TPB, 2) void fused_attn(float* __restrict__ out,
                                                     float* __restrict__ out_sim) {
    extern __shared__ float sm[];
    float* expc = sm;
    float* expr = sm + 8000;
    unsigned long long* qsd   = (unsigned long long*)(sm + 16000);
    float* pav  = sm + 16512;
    unsigned long long* scrvd = (unsigned long long*)(sm + 16000);
    float* misc = sm + 18048;

    const int tid  = threadIdx.x;
    const int lane = tid & 31;
    const int wrp  = tid >> 5;
    const int i0   = blockIdx.x * ROWS;

    // phase A map: branch x 128 j-threads (4 j each, 4 passes)
    const int bA = tid >> 7;            // 0=cls, 1=reg (warp-uniform)
    const int jt = tid & 127;
    const float* ktA = bA ? g_ktr : g_ktc;
    float* ebA = bA ? expr : expc;
    const int boff = bA * 128;

    // B1/C cell ownership: thread owns j-quads {tid, tid+256} (tid+256 active iff <500),
    // all 4 rows each. Sim accumulates in registers across heads.
    float4 simreg[2][ROWS];
    #pragma unroll
    for (int p2 = 0; p2 < 2; ++p2)
        #pragma unroll
        for (int r = 0; r < ROWS; ++r) simreg[p2][r] = make_float4(0.f, 0.f, 0.f, 0.f);

    for (int h = 0; h < H_NUM; ++h) {
        // ======== phase A: scores -> exp -> row sums (k streamed from L2, FFMA2) ========
        if (tid < 16) misc[tid] = 0.f;
        {   // q tiles duplicated: 256 entries = 2 branches x 4 rows x 32 ch
            int b2 = tid >> 7, r = (tid >> 5) & 3, kk = tid & 31;
            const float* qsrc = b2 ? g_qnr : g_qnc;
            float q = qsrc[(i0 + r) * C_DIM + h * 32 + kk];
            qsd[tid] = pack2(q, q);
        }
        __syncthreads();

        float psum[ROWS];
        #pragma unroll
        for (int r = 0; r < ROWS; ++r) psum[r] = 0.f;

        #pragma unroll
        for (int pass = 0; pass < 4; ++pass) {
            int j = pass * 512 + jt * 4;
            if (j < N_TOK) {
                unsigned long long c2[ROWS][2];
                #pragma unroll
                for (int r = 0; r < ROWS; ++r) { c2[r][0] = 0ULL; c2[r][1] = 0ULL; }
                const float* ktb = ktA + (size_t)(h * 32) * KT_LD + j;
                #pragma unroll
                for (int cg = 0; cg < 8; ++cg) {
                    ulonglong2 kv[4];
                    #pragma unroll
                    for (int u = 0; u < 4; ++u)
                        kv[u] = *(const ulonglong2*)&ktb[(size_t)(cg * 4 + u) * KT_LD];
                    #pragma unroll
                    for (int u = 0; u < 4; ++u) {
                        #pragma unroll
                        for (int r = 0; r < ROWS; ++r) {
                            unsigned long long qd = qsd[boff + r * 32 + cg * 4 + u];
                            c2[r][0] = fma2(qd, kv[u].x, c2[r][0]);
                            c2[r][1] = fma2(qd, kv[u].y, c2[r][1]);
                        }
                    }
                }
                #pragma unroll
                for (int r = 0; r < ROWS; ++r) {
                    float2 lo = unpack2(c2[r][0]);
                    float2 hi = unpack2(c2[r][1]);
                    float4 e;
                    e.x = __expf(fmaf(lo.x, 25.f, -25.f));
                    e.y = __expf(fmaf(lo.y, 25.f, -25.f));
                    e.z = __expf(fmaf(hi.x, 25.f, -25.f));
                    e.w = __expf(fmaf(hi.y, 25.f, -25.f));
                    *(float4*)&ebA[r * 2000 + j] = e;
                    psum[r] += (e.x + e.y) + (e.z + e.w);
                }
            }
        }
        #pragma unroll
        for (int r = 0; r < ROWS; ++r) {
            float s = warpSum(psum[r]);
            if (lane == 0) atomicAdd(&misc[bA * 8 + r], s);
        }
        __syncthreads();
        if (tid < 16) misc[tid] = 1.0f / misc[tid];
        __syncthreads();

        // ======== phase B1: combine + mask (p overwrites expc) + sim accumulate in regs ========
        #pragma unroll
        for (int p2 = 0; p2 < 2; ++p2) {
            int jq = tid + p2 * 256;
            if (jq < 500) {
                int j = jq * 4;
                #pragma unroll
                for (int r = 0; r < ROWS; ++r) {
                    float4 ec = *(const float4*)&expc[r * 2000 + j];
                    float4 er = *(const float4*)&expr[r * 2000 + j];
                    float ic = misc[r], ir = misc[8 + r];
                    float4 p;
                    p.x = 0.5f * fmaf(ec.x, ic, er.x * ir);
                    p.y = 0.5f * fmaf(ec.y, ic, er.y * ir);
                    p.z = 0.5f * fmaf(ec.z, ic, er.z * ir);
                    p.w = 0.5f * fmaf(ec.w, ic, er.w * ir);
                    int i = i0 + r, bs = (i / 10) * 10;
                    if (!((j + 0 == i) || (j + 0 < bs) || (j + 0 >= bs + 9))) p.x = 0.f;
                    if (!((j + 1 == i) || (j + 1 < bs) || (j + 1 >= bs + 9))) p.y = 0.f;
                    if (!((j + 2 == i) || (j + 2 < bs) || (j + 2 >= bs + 9))) p.z = 0.f;
                    if (!((j + 3 == i) || (j + 3 < bs) || (j + 3 >= bs + 9))) p.w = 0.f;
                    simreg[p2][r].x += p.x;
                    simreg[p2][r].y += p.y;
                    simreg[p2][r].z += p.z;
                    simreg[p2][r].w += p.w;
                    *(float4*)&expc[r * 2000 + j] = p;
                }
            }
        }
        __syncthreads();

        // ======== phase B2: AV (x = p @ v), 8 warps x 256-j slices, FFMA2 ========
        {
            int jbase = wrp * 256;
            int cnt = N_TOK - jbase; if (cnt > 256) cnt = 256;
            unsigned long long acc2[ROWS];
            #pragma unroll
            for (int r = 0; r < ROWS; ++r) acc2[r] = 0ULL;
            const float* vp = g_yc + 512 + h * 32 + lane;
            for (int jj = 0; jj < cnt; jj += 4) {
                int j = jbase + jj;
                float v0 = vp[(size_t)(j + 0) * C3];
                float v1 = vp[(size_t)(j + 1) * C3];
                float v2 = vp[(size_t)(j + 2) * C3];
                float v3 = vp[(size_t)(j + 3) * C3];
                unsigned long long vA = pack2(v0, v1);
                unsigned long long vB = pack2(v2, v3);
                #pragma unroll
                for (int r = 0; r < ROWS; ++r) {
                    ulonglong2 p2v = *(const ulonglong2*)&expc[r * 2000 + j];  // broadcast
                    acc2[r] = fma2(p2v.x, vA, acc2[r]);
                    acc2[r] = fma2(p2v.y, vB, acc2[r]);
                }
            }
            #pragma unroll
            for (int r = 0; r < ROWS; ++r) {
                float2 t = unpack2(acc2[r]);
                pav[wrp * 128 + r * 32 + lane] = t.x + t.y;
            }
        }
        __syncthreads();
        if (tid < 128) {
            int r = tid >> 5, d = tid & 31;
            float s = 0.f;
            #pragma unroll
            for (int w2 = 0; w2 < 8; ++w2) s += pav[w2 * 128 + tid];
            out[(size_t)(i0 + r) * 512 + h * 32 + d] = s;
        }
        // no trailing sync: next head's post-q-load sync orders pav/qsd reuse
    }

    // ======== phase C: raw = vn.vn^T mask + sim_round2 (sim lives in registers) ========
    __syncthreads();   // all heads done: pav/qsd region free for scrvd
    {   // vn rows of this block -> scrvd duplicated (4 rows x 256 ch)
        int r = tid >> 6, cc = (tid & 63) * 4;
        float4 v = *(const float4*)&g_vn[(i0 + r) * C_DIM + cc];
        scrvd[r * 256 + cc + 0] = pack2(v.x, v.x);
        scrvd[r * 256 + cc + 1] = pack2(v.y, v.y);
        scrvd[r * 256 + cc + 2] = pack2(v.z, v.z);
        scrvd[r * 256 + cc + 3] = pack2(v.w, v.w);
    }
    if (tid >= 16 && tid < 32) misc[tid] = 0.f;   // clear [16..31]
    __syncthreads();
    {   // denominators: sum_j exp(sim[r][j]) from registers
        float srow[ROWS];
        #pragma unroll
        for (int r = 0; r < ROWS; ++r) srow[r] = 0.f;
        #pragma unroll
        for (int p2 = 0; p2 < 2; ++p2) {
            int jq = tid + p2 * 256;
            if (jq < 500) {
                #pragma unroll
                for (int r = 0; r < ROWS; ++r) {
                    float4 sb = simreg[p2][r];
                    srow[r] += __expf(sb.x) + __expf(sb.y) + __expf(sb.z) + __expf(sb.w);
                }
            }
        }
        #pragma unroll
        for (int r = 0; r < ROWS; ++r) {
            float s = warpSum(srow[r]);
            if (lane == 0) atomicAdd(&misc[16 + r], s);
        }
    }
    __syncthreads();
    if (tid < 4) misc[16 + tid] = 1.0f / misc[16 + tid];
    __syncthreads();
    {   // raw rows (vnt streamed from L2, FFMA2, shared across 4 rows), mask + exp
        float tot[ROWS];
        #pragma unroll
        for (int r = 0; r < ROWS; ++r) tot[r] = 0.f;
        #pragma unroll
        for (int p2 = 0; p2 < 2; ++p2) {
            int jq = tid + p2 * 256;
            if (jq < 500) {
                int j = jq * 4;
                unsigned long long c2[ROWS][2];
                #pragma unroll
                for (int r = 0; r < ROWS; ++r) { c2[r][0] = 0ULL; c2[r][1] = 0ULL; }
                const float* vt = g_vnt + j;
                for (int cg = 0; cg < 64; ++cg) {
                    ulonglong2 kv[4];
                    #pragma unroll
                    for (int u = 0; u < 4; ++u)
                        kv[u] = *(const ulonglong2*)&vt[(size_t)(cg * 4 + u) * KT_LD];
                    #pragma unroll
                    for (int u = 0; u < 4; ++u) {
                        #pragma unroll
                        for (int r = 0; r < ROWS; ++r) {
                            unsigned long long qd = scrvd[r * 256 + cg * 4 + u];
                            c2[r][0] = fma2(qd, kv[u].x, c2[r][0]);
                            c2[r][1] = fma2(qd, kv[u].y, c2[r][1]);
                        }
                    }
                }
                #pragma unroll
                for (int r = 0; r < ROWS; ++r) {
                    float2 lo = unpack2(c2[r][0]);
                    float2 hi = unpack2(c2[r][1]);
                    float4 sb = simreg[p2][r];
                    float inv = misc[16 + r];
                    // raw_mean > 0.75  <=>  raw (sum over 8 heads) > 6.0
                    float t0 = (lo.x > 6.0f) ? __expf(sb.x) * inv : 0.f;
                    float t1 = (lo.y > 6.0f) ? __expf(sb.y) * inv : 0.f;
                    float t2 = (hi.x > 6.0f) ? __expf(sb.z) * inv : 0.f;
                    float t3 = (hi.y > 6.0f) ? __expf(sb.w) * inv : 0.f;
                    simreg[p2][r] = make_float4(t0, t1, t2, t3);
                    tot[r] += (t0 + t1) + (t2 + t3);
                }
            }
        }
        #pragma unroll
        for (int r = 0; r < ROWS; ++r) {
            float s = warpSum(tot[r]);
            if (lane == 0) atomicAdd(&misc[24 + r], s);
        }
    }
    __syncthreads();
    if (tid < 4) misc[24 + tid] = 1.0f / (misc[24 + tid] + 1e-8f);
    __syncthreads();
    {   // final store straight from registers (coalesced float4 per lane)
        #pragma unroll
        for (int p2 = 0; p2 < 2; ++p2) {
            int jq = tid + p2 * 256;
            if (jq < 500) {
                int j = jq * 4;
                #pragma unroll
                for (int r = 0; r < ROWS; ++r) {
                    float invt = misc[24 + r];
                    float4 sb = simreg[p2][r];
                    sb.x *= invt; sb.y *= invt; sb.z *= invt; sb.w *= invt;
                    *(float4*)&out_sim[(size_t)(i0 + r) * 2000 + j] = sb;
                }
            }
        }
    }
}

// ---------------- launch ----------------
extern "C" void kernel_launch(void* const* d_in, const int* in_sizes, int n_in,
                              void* d_out, int out_size) {
    const float* x_cls = (const float*)d_in[0];
    const float* x_reg = (const float*)d_in[1];
    const float* Wc    = (const float*)d_in[2];
    const float* Wr    = (const float*)d_in[3];
    float* out     = (float*)d_out;
    float* out_sim = out + (size_t)N_TOK * 512;

    float *yc, *yr;
    cudaGetSymbolAddress((void**)&yc, g_yc);
    cudaGetSymbolAddress((void**)&yr, g_yr);

    cudaFuncSetAttribute(fused_attn, cudaFuncAttributeMaxDynamicSharedMemorySize,
                         SMEM_FLOATS * 4);

    // 1) QKV projections
    sgemm_nn<<<dim3(12, 32), 256>>>(x_cls, Wc, yc, N_TOK, C3, C_DIM, C_DIM, C3, C3);
    sgemm_nn<<<dim3(12, 32), 256>>>(x_reg, Wr, yr, N_TOK, C3, C_DIM, C_DIM, C3, C3);

    // 2) per-head L2 normalize + transposes (+ x_ori half of out)
    normalize_kernel<<<N_TOK, 256>>>(yc, yr, out);

    // 3) fully fused attention: scores -> softmax -> mask -> sim -> AV -> raw -> sim_round2
    fused_attn<<<NCTA, TPB, SMEM_FLOATS * 4>>>(out, out_sim);
}